// round 2
// baseline (speedup 1.0000x reference)
#include <cuda_runtime.h>
#include <math.h>

#define NMAXN 100000
#define NMAXE 1600000
#define INCH 61
#define OC 64
#define BN_EPS 1e-5f

// ------------- static device scratch (no allocation allowed) -------------
__device__ float d_A[NMAXN * OC];    // x@W1[:61] + pos@W1[61:]
__device__ float d_Bp[NMAXN * OC];   // pos@W1[61:]
__device__ int   d_deg[NMAXN];
__device__ int   d_rowptr[NMAXN + 1];
__device__ int   d_cursor[NMAXN];
__device__ int   d_csrc[NMAXE];      // src node per CSR slot (grouped by dst)
__device__ float d_graw[NMAXE];      // gate pre-BN value per CSR slot
__device__ float d_sumz[OC];
__device__ float d_sumz2[OC];
__device__ float d_scale1[OC];
__device__ float d_shift1[OC];
__device__ float d_gstats[2];
__device__ float d_gparams[2];       // gate BN scale, shift

__device__ __forceinline__ float silu_f(float t) {
    return t / (1.0f + __expf(-t));
}

// ------------- K0: zero counters / stats -------------
__global__ void k_init(int n) {
    int i = blockIdx.x * blockDim.x + threadIdx.x;
    int st = gridDim.x * blockDim.x;
    for (int t = i; t < n; t += st) d_deg[t] = 0;
    if (i < OC) { d_sumz[i] = 0.0f; d_sumz2[i] = 0.0f; }
    if (i < 2)  { d_gstats[i] = 0.0f; }
}

// ------------- K1: per-node transform A = x@W1[:61]+pos@W1[61:], B = pos@W1[61:] -------------
__global__ void k_node(const float* __restrict__ x, const float* __restrict__ pos,
                       const float* __restrict__ W1, int n) {
    __shared__ float sW[64 * OC];
    for (int i = threadIdx.x; i < 64 * OC; i += blockDim.x) sW[i] = W1[i];
    __syncthreads();
    int lane = threadIdx.x & 31;
    int wid  = (blockIdx.x * blockDim.x + threadIdx.x) >> 5;
    int nw   = (gridDim.x * blockDim.x) >> 5;
    int c0 = lane, c1 = lane + 32;
    for (int nd = wid; nd < n; nd += nw) {
        float a0 = 0.f, a1 = 0.f, b0 = 0.f, b1v = 0.f;
        const float* xr = x + (long long)nd * INCH;
        #pragma unroll
        for (int k = 0; k < INCH; k++) {
            float xv = __ldg(xr + k);
            a0 = fmaf(xv, sW[k * OC + c0], a0);
            a1 = fmaf(xv, sW[k * OC + c1], a1);
        }
        const float* pr = pos + (long long)nd * 3;
        #pragma unroll
        for (int k = 0; k < 3; k++) {
            float pv = __ldg(pr + k);
            b0  = fmaf(pv, sW[(INCH + k) * OC + c0], b0);
            b1v = fmaf(pv, sW[(INCH + k) * OC + c1], b1v);
        }
        d_A[nd * OC + c0] = a0 + b0;
        d_A[nd * OC + c1] = a1 + b1v;
        d_Bp[nd * OC + c0] = b0;
        d_Bp[nd * OC + c1] = b1v;
    }
}

// ------------- K2: in-degree histogram (edge_index is int32: [2, E]) -------------
__global__ void k_count(const int* __restrict__ ei, int e, int n) {
    int i = blockIdx.x * blockDim.x + threadIdx.x;
    int st = gridDim.x * blockDim.x;
    for (; i < e; i += st) {
        unsigned d = (unsigned)ei[e + i];  // dst row
        if (d < (unsigned)n)
            atomicAdd(&d_deg[d], 1);
    }
}

// ------------- K3: exclusive scan -> rowptr, cursor (single block) -------------
__global__ void k_scan(int n) {
    __shared__ int sh[32];
    __shared__ int carry;
    int t = threadIdx.x;
    int lane = t & 31, w = t >> 5;
    if (t == 0) carry = 0;
    __syncthreads();
    int nchunks = (n + 1023) / 1024;
    for (int c = 0; c < nchunks; c++) {
        int idx = c * 1024 + t;
        int v = (idx < n) ? d_deg[idx] : 0;
        int xv = v;
        #pragma unroll
        for (int off = 1; off < 32; off <<= 1) {
            int y = __shfl_up_sync(0xffffffffu, xv, off);
            if (lane >= off) xv += y;
        }
        if (lane == 31) sh[w] = xv;
        __syncthreads();
        if (w == 0) {
            int y2 = sh[lane];
            #pragma unroll
            for (int off = 1; off < 32; off <<= 1) {
                int z = __shfl_up_sync(0xffffffffu, y2, off);
                if (lane >= off) y2 += z;
            }
            sh[lane] = y2;
        }
        __syncthreads();
        int woff = (w > 0) ? sh[w - 1] : 0;
        int incl = xv + woff;
        int base = carry;
        __syncthreads();
        if (idx < n) {
            int ex = base + incl - v;
            d_rowptr[idx] = ex;
            d_cursor[idx] = ex;
        }
        if (t == 1023) carry = base + incl;
        __syncthreads();
    }
    if (t == 0) d_rowptr[n] = carry;
}

// ------------- K4: scatter src ids into CSR slots -------------
__global__ void k_scatter(const int* __restrict__ ei, int e, int n) {
    int i = blockIdx.x * blockDim.x + threadIdx.x;
    int st = gridDim.x * blockDim.x;
    for (; i < e; i += st) {
        unsigned s = (unsigned)ei[i];
        unsigned d = (unsigned)ei[e + i];
        if (s >= (unsigned)n || d >= (unsigned)n) continue;
        int p = atomicAdd(&d_cursor[d], 1);
        d_csrc[p] = (int)s;
    }
}

// ------------- K5: per-channel sum/sumsq of z over all edges -------------
__global__ void k_zstats(const float* __restrict__ b1, int n) {
    int lane = threadIdx.x & 31;
    int wid  = (blockIdx.x * blockDim.x + threadIdx.x) >> 5;
    int nw   = (gridDim.x * blockDim.x) >> 5;
    int c0 = lane, c1 = lane + 32;
    float bias0 = b1[c0], bias1 = b1[c1];
    float sz0 = 0.f, sz1 = 0.f, sq0 = 0.f, sq1 = 0.f;
    for (int nd = wid; nd < n; nd += nw) {
        int r0 = d_rowptr[nd], r1 = d_rowptr[nd + 1];
        if (r0 == r1) continue;
        float o0 = bias0 - d_Bp[nd * OC + c0];
        float o1 = bias1 - d_Bp[nd * OC + c1];
        for (int j = r0; j < r1; j++) {
            int s = d_csrc[j];
            float z0 = d_A[s * OC + c0] + o0;
            float z1 = d_A[s * OC + c1] + o1;
            sz0 += z0; sq0 = fmaf(z0, z0, sq0);
            sz1 += z1; sq1 = fmaf(z1, z1, sq1);
        }
    }
    atomicAdd(&d_sumz[c0], sz0);  atomicAdd(&d_sumz2[c0], sq0);
    atomicAdd(&d_sumz[c1], sz1);  atomicAdd(&d_sumz2[c1], sq1);
}

// ------------- K6: finalize BN1 params -------------
__global__ void k_bn1(const float* __restrict__ g1, const float* __restrict__ be1, float Ef) {
    int c = threadIdx.x;
    float mu  = d_sumz[c] / Ef;
    float var = d_sumz2[c] / Ef - mu * mu;
    float sc  = g1[c] * rsqrtf(var + BN_EPS);
    d_scale1[c] = sc;
    d_shift1[c] = be1[c] - mu * sc;
}

// ------------- K7: gate_raw per edge + gate stats -------------
__global__ void k_gate(const float* __restrict__ b1, const float* __restrict__ Wg,
                       const float* __restrict__ bg, int n) {
    int lane = threadIdx.x & 31;
    int wid  = (blockIdx.x * blockDim.x + threadIdx.x) >> 5;
    int nw   = (gridDim.x * blockDim.x) >> 5;
    int c0 = lane, c1 = lane + 32;
    float bias0 = b1[c0], bias1 = b1[c1];
    float sc0 = d_scale1[c0], sc1 = d_scale1[c1];
    float sh0 = d_shift1[c0], sh1 = d_shift1[c1];
    float w0 = Wg[c0], w1 = Wg[c1];
    float bgv = bg[0];
    float sg = 0.f, sg2 = 0.f;
    for (int nd = wid; nd < n; nd += nw) {
        int r0 = d_rowptr[nd], r1 = d_rowptr[nd + 1];
        if (r0 == r1) continue;
        float o0 = bias0 - d_Bp[nd * OC + c0];
        float o1 = bias1 - d_Bp[nd * OC + c1];
        for (int j = r0; j < r1; j++) {
            int s = d_csrc[j];
            float z0 = d_A[s * OC + c0] + o0;
            float z1 = d_A[s * OC + c1] + o1;
            float t0 = fmaf(z0, sc0, sh0);
            float t1 = fmaf(z1, sc1, sh1);
            float p = silu_f(t0) * w0 + silu_f(t1) * w1;
            #pragma unroll
            for (int off = 16; off; off >>= 1)
                p += __shfl_xor_sync(0xffffffffu, p, off);
            p += bgv;
            if (lane == 0) {
                d_graw[j] = p;
                sg += p;
                sg2 = fmaf(p, p, sg2);
            }
        }
    }
    if (lane == 0) {
        atomicAdd(&d_gstats[0], sg);
        atomicAdd(&d_gstats[1], sg2);
    }
}

// ------------- K8: finalize gate BN params -------------
__global__ void k_bng(const float* __restrict__ gg, const float* __restrict__ bgb, float Ef) {
    float mu  = d_gstats[0] / Ef;
    float var = d_gstats[1] / Ef - mu * mu;
    float sc  = gg[0] * rsqrtf(var + BN_EPS);
    d_gparams[0] = sc;
    d_gparams[1] = bgb[0] - mu * sc;
}

// ------------- K9: segment softmax + weighted aggregate (warp per node, no atomics) -------------
__global__ void k_agg(const float* __restrict__ b1, float* __restrict__ out, int n) {
    int lane = threadIdx.x & 31;
    int wid  = (blockIdx.x * blockDim.x + threadIdx.x) >> 5;
    int nw   = (gridDim.x * blockDim.x) >> 5;
    int c0 = lane, c1 = lane + 32;
    float bias0 = b1[c0], bias1 = b1[c1];
    float sc0 = d_scale1[c0], sc1 = d_scale1[c1];
    float sh0 = d_shift1[c0], sh1 = d_shift1[c1];
    float gsc = d_gparams[0], gsh = d_gparams[1];
    for (int nd = wid; nd < n; nd += nw) {
        int r0 = d_rowptr[nd], r1 = d_rowptr[nd + 1];
        if (r0 == r1) {
            out[nd * OC + c0] = 0.0f;
            out[nd * OC + c1] = 0.0f;
            continue;
        }
        // pass 1: segment max of gate
        float m = -INFINITY;
        for (int j = r0 + lane; j < r1; j += 32) {
            float g = silu_f(fmaf(d_graw[j], gsc, gsh));
            m = fmaxf(m, g);
        }
        #pragma unroll
        for (int off = 16; off; off >>= 1)
            m = fmaxf(m, __shfl_xor_sync(0xffffffffu, m, off));
        // pass 2: sum of exp
        float ssum = 0.f;
        for (int j = r0 + lane; j < r1; j += 32) {
            float g = silu_f(fmaf(d_graw[j], gsc, gsh));
            ssum += __expf(g - m);
        }
        #pragma unroll
        for (int off = 16; off; off >>= 1)
            ssum += __shfl_xor_sync(0xffffffffu, ssum, off);
        float inv = 1.0f / (ssum + 1e-16f);
        // pass 3: weighted aggregate
        float o0 = bias0 - d_Bp[nd * OC + c0];
        float o1 = bias1 - d_Bp[nd * OC + c1];
        float acc0 = 0.f, acc1 = 0.f;
        for (int base = r0; base < r1; base += 32) {
            int j = base + lane;
            float ee = 0.f;
            int sidx = 0;
            if (j < r1) {
                float g = silu_f(fmaf(d_graw[j], gsc, gsh));
                ee = __expf(g - m) * inv;
                sidx = d_csrc[j];
            }
            int cnt = min(32, r1 - base);
            for (int k = 0; k < cnt; k++) {
                float w = __shfl_sync(0xffffffffu, ee, k);
                int s   = __shfl_sync(0xffffffffu, sidx, k);
                float z0 = d_A[s * OC + c0] + o0;
                float z1 = d_A[s * OC + c1] + o1;
                float h0 = silu_f(fmaf(z0, sc0, sh0));
                float h1 = silu_f(fmaf(z1, sc1, sh1));
                acc0 = fmaf(w, h0, acc0);
                acc1 = fmaf(w, h1, acc1);
            }
        }
        out[nd * OC + c0] = acc0;
        out[nd * OC + c1] = acc1;
    }
}

// ------------- launch -------------
extern "C" void kernel_launch(void* const* d_in, const int* in_sizes, int n_in,
                              void* d_out, int out_size) {
    const float* x   = (const float*)d_in[0];
    const float* pos = (const float*)d_in[1];
    const int*   ei  = (const int*)d_in[2];   // int32 [2, E] (JAX x64 disabled)
    const float* W1  = (const float*)d_in[3];
    const float* b1  = (const float*)d_in[4];
    const float* g1  = (const float*)d_in[5];
    const float* be1 = (const float*)d_in[6];
    const float* Wg  = (const float*)d_in[7];
    const float* bg  = (const float*)d_in[8];
    const float* gg  = (const float*)d_in[9];
    const float* bgb = (const float*)d_in[10];
    float* out = (float*)d_out;

    int n = in_sizes[0] / INCH;   // 100000
    int e = in_sizes[2] / 2;      // 1600000

    k_init   <<<256, 256>>>(n);
    k_node   <<<512, 256>>>(x, pos, W1, n);
    k_count  <<<512, 256>>>(ei, e, n);
    k_scan   <<<1, 1024>>>(n);
    k_scatter<<<512, 256>>>(ei, e, n);
    k_zstats <<<512, 256>>>(b1, n);
    k_bn1    <<<1, 64>>>(g1, be1, (float)e);
    k_gate   <<<512, 256>>>(b1, Wg, bg, n);
    k_bng    <<<1, 1>>>(gg, bgb, (float)e);
    k_agg    <<<512, 256>>>(b1, out, n);
}

// round 3
// speedup vs baseline: 1.2217x; 1.2217x over previous
#include <cuda_runtime.h>
#include <math.h>

#define NMAXN 100000
#define NMAXE 1600000
#define INCH 61
#define OC 64
#define BN_EPS 1e-5f
#define SCAN_BLK 1024

// ------------- static device scratch (no allocation allowed) -------------
__device__ float2 d_A[NMAXN * 32];    // x@W1[:61] + pos@W1[61:], channel pair (2l, 2l+1)
__device__ float2 d_Bp[NMAXN * 32];   // pos@W1[61:]
__device__ int    d_deg[NMAXN];
__device__ int    d_scanned[NMAXN];   // in-block inclusive scan
__device__ int    d_bsum[128];
__device__ int    d_rowptr[NMAXN + 1];
__device__ int    d_cursor[NMAXN];
__device__ int    d_csrc[NMAXE];      // src node per CSR slot (grouped by dst)
__device__ float  d_graw[NMAXE];      // gate value per CSR slot (staged: raw -> g -> e)
__device__ float  d_sumz[OC];
__device__ float  d_sumz2[OC];
__device__ float2 d_scale1[32];
__device__ float2 d_shift1[32];
__device__ float  d_gstats[2];
__device__ float  d_gparams[2];       // gate BN scale, shift

__device__ __forceinline__ float silu_f(float t) {
    return t / (1.0f + __expf(-t));
}

// ------------- K0: zero counters / stats -------------
__global__ void k_init(int n) {
    int i = blockIdx.x * blockDim.x + threadIdx.x;
    int st = gridDim.x * blockDim.x;
    for (int t = i; t < n; t += st) d_deg[t] = 0;
    if (i < OC) { d_sumz[i] = 0.0f; d_sumz2[i] = 0.0f; }
    if (i < 2)  { d_gstats[i] = 0.0f; }
}

// ------------- K1: per-node transform -------------
__global__ void k_node(const float* __restrict__ x, const float* __restrict__ pos,
                       const float* __restrict__ W1, int n) {
    __shared__ float2 sW[64 * 32];   // sW[k*32+l] = channels (2l, 2l+1) of row k
    const float2* W2 = (const float2*)W1;
    for (int i = threadIdx.x; i < 64 * 32; i += blockDim.x) sW[i] = W2[i];
    __syncthreads();
    int lane = threadIdx.x & 31;
    int wid  = (blockIdx.x * blockDim.x + threadIdx.x) >> 5;
    int nw   = (gridDim.x * blockDim.x) >> 5;
    for (int nd = wid; nd < n; nd += nw) {
        float a0 = 0.f, a1 = 0.f, b0 = 0.f, b1v = 0.f;
        const float* xr = x + (long long)nd * INCH;
        #pragma unroll
        for (int k = 0; k < INCH; k++) {
            float xv = __ldg(xr + k);
            float2 w = sW[k * 32 + lane];
            a0 = fmaf(xv, w.x, a0);
            a1 = fmaf(xv, w.y, a1);
        }
        const float* pr = pos + (long long)nd * 3;
        #pragma unroll
        for (int k = 0; k < 3; k++) {
            float pv = __ldg(pr + k);
            float2 w = sW[(INCH + k) * 32 + lane];
            b0  = fmaf(pv, w.x, b0);
            b1v = fmaf(pv, w.y, b1v);
        }
        d_A[nd * 32 + lane]  = make_float2(a0 + b0, a1 + b1v);
        d_Bp[nd * 32 + lane] = make_float2(b0, b1v);
    }
}

// ------------- K2: in-degree histogram (edge_index is int32: [2, E]) -------------
__global__ void k_count(const int* __restrict__ ei, int e, int n) {
    int i = blockIdx.x * blockDim.x + threadIdx.x;
    int st = gridDim.x * blockDim.x;
    for (; i < e; i += st) {
        unsigned d = (unsigned)ei[e + i];
        if (d < (unsigned)n)
            atomicAdd(&d_deg[d], 1);
    }
}

// ------------- K3a: per-block inclusive scan of deg -------------
__global__ void k_scanA(int n) {
    __shared__ int sh[32];
    int t = threadIdx.x, lane = t & 31, w = t >> 5;
    int idx = blockIdx.x * SCAN_BLK + t;
    int v = (idx < n) ? d_deg[idx] : 0;
    int xv = v;
    #pragma unroll
    for (int off = 1; off < 32; off <<= 1) {
        int y = __shfl_up_sync(0xffffffffu, xv, off);
        if (lane >= off) xv += y;
    }
    if (lane == 31) sh[w] = xv;
    __syncthreads();
    if (w == 0) {
        int y2 = sh[lane];
        #pragma unroll
        for (int off = 1; off < 32; off <<= 1) {
            int z = __shfl_up_sync(0xffffffffu, y2, off);
            if (lane >= off) y2 += z;
        }
        sh[lane] = y2;
    }
    __syncthreads();
    int incl = xv + ((w > 0) ? sh[w - 1] : 0);
    if (idx < n) d_scanned[idx] = incl;
    if (t == SCAN_BLK - 1) d_bsum[blockIdx.x] = incl;
}

// ------------- K3b: exclusive scan of block sums (1 block, 128 threads) -------------
__global__ void k_scanB(int nb, int n) {
    __shared__ int sw[4];
    int t = threadIdx.x, lane = t & 31, w = t >> 5;
    int v = (t < nb) ? d_bsum[t] : 0;
    int xv = v;
    #pragma unroll
    for (int off = 1; off < 32; off <<= 1) {
        int y = __shfl_up_sync(0xffffffffu, xv, off);
        if (lane >= off) xv += y;
    }
    if (lane == 31) sw[w] = xv;
    __syncthreads();
    if (t == 0) {
        int run = 0;
        #pragma unroll
        for (int i = 0; i < 4; i++) { int tmp = sw[i]; sw[i] = run; run += tmp; }
    }
    __syncthreads();
    int incl = xv + sw[w];
    if (t < nb) d_bsum[t] = incl - v;     // exclusive offset per block
    if (t == nb - 1) d_rowptr[n] = incl;  // total edge count
}

// ------------- K3c: finalize rowptr/cursor -------------
__global__ void k_scanC(int n) {
    int idx = blockIdx.x * SCAN_BLK + threadIdx.x;
    if (idx < n) {
        int ex = d_scanned[idx] - d_deg[idx] + d_bsum[blockIdx.x];
        d_rowptr[idx] = ex;
        d_cursor[idx] = ex;
    }
}

// ------------- K4: scatter src ids into CSR slots -------------
__global__ void k_scatter(const int* __restrict__ ei, int e, int n) {
    int i = blockIdx.x * blockDim.x + threadIdx.x;
    int st = gridDim.x * blockDim.x;
    for (; i < e; i += st) {
        unsigned s = (unsigned)ei[i];
        unsigned d = (unsigned)ei[e + i];
        if (s >= (unsigned)n || d >= (unsigned)n) continue;
        int p = atomicAdd(&d_cursor[d], 1);
        d_csrc[p] = (int)s;
    }
}

// ------------- K5: per-channel sum/sumsq of z over all edges -------------
__global__ void k_zstats(const float* __restrict__ b1, int n) {
    int lane = threadIdx.x & 31;
    int wid  = (blockIdx.x * blockDim.x + threadIdx.x) >> 5;
    int nw   = (gridDim.x * blockDim.x) >> 5;
    float2 bias = ((const float2*)b1)[lane];
    float sz0 = 0.f, sz1 = 0.f, sq0 = 0.f, sq1 = 0.f;
    for (int nd = wid; nd < n; nd += nw) {
        int r0 = d_rowptr[nd], r1 = d_rowptr[nd + 1];
        if (r0 == r1) continue;
        float2 bp = d_Bp[nd * 32 + lane];
        float ox = bias.x - bp.x, oy = bias.y - bp.y;
        int j = r0;
        for (; j + 4 <= r1; j += 4) {
            int s0 = d_csrc[j], s1 = d_csrc[j + 1], s2 = d_csrc[j + 2], s3 = d_csrc[j + 3];
            float2 a0 = d_A[s0 * 32 + lane];
            float2 a1 = d_A[s1 * 32 + lane];
            float2 a2 = d_A[s2 * 32 + lane];
            float2 a3 = d_A[s3 * 32 + lane];
            float z;
            z = a0.x + ox; sz0 += z; sq0 = fmaf(z, z, sq0);
            z = a0.y + oy; sz1 += z; sq1 = fmaf(z, z, sq1);
            z = a1.x + ox; sz0 += z; sq0 = fmaf(z, z, sq0);
            z = a1.y + oy; sz1 += z; sq1 = fmaf(z, z, sq1);
            z = a2.x + ox; sz0 += z; sq0 = fmaf(z, z, sq0);
            z = a2.y + oy; sz1 += z; sq1 = fmaf(z, z, sq1);
            z = a3.x + ox; sz0 += z; sq0 = fmaf(z, z, sq0);
            z = a3.y + oy; sz1 += z; sq1 = fmaf(z, z, sq1);
        }
        for (; j < r1; j++) {
            float2 a = d_A[d_csrc[j] * 32 + lane];
            float z;
            z = a.x + ox; sz0 += z; sq0 = fmaf(z, z, sq0);
            z = a.y + oy; sz1 += z; sq1 = fmaf(z, z, sq1);
        }
    }
    atomicAdd(&d_sumz[2 * lane],      sz0);
    atomicAdd(&d_sumz[2 * lane + 1],  sz1);
    atomicAdd(&d_sumz2[2 * lane],     sq0);
    atomicAdd(&d_sumz2[2 * lane + 1], sq1);
}

// ------------- K6: finalize BN1 params -------------
__global__ void k_bn1(const float* __restrict__ g1, const float* __restrict__ be1, float Ef) {
    int c = threadIdx.x;
    float mu  = d_sumz[c] / Ef;
    float var = d_sumz2[c] / Ef - mu * mu;
    float sc  = g1[c] * rsqrtf(var + BN_EPS);
    ((float*)d_scale1)[c] = sc;
    ((float*)d_shift1)[c] = be1[c] - mu * sc;
}

// ------------- K7: gate_raw per edge + gate stats -------------
__global__ void k_gate(const float* __restrict__ b1, const float* __restrict__ Wg,
                       const float* __restrict__ bg, int n) {
    int lane = threadIdx.x & 31;
    int wid  = (blockIdx.x * blockDim.x + threadIdx.x) >> 5;
    int nw   = (gridDim.x * blockDim.x) >> 5;
    float2 bias = ((const float2*)b1)[lane];
    float2 sc = d_scale1[lane];
    float2 sh = d_shift1[lane];
    float2 wg = ((const float2*)Wg)[lane];
    float bgv = bg[0];
    float sg = 0.f, sg2 = 0.f;
    for (int nd = wid; nd < n; nd += nw) {
        int r0 = d_rowptr[nd], r1 = d_rowptr[nd + 1];
        if (r0 == r1) continue;
        float2 bp = d_Bp[nd * 32 + lane];
        float ox = bias.x - bp.x, oy = bias.y - bp.y;
        int j = r0;
        for (; j + 2 <= r1; j += 2) {
            int s0 = d_csrc[j], s1 = d_csrc[j + 1];
            float2 a0 = d_A[s0 * 32 + lane];
            float2 a1 = d_A[s1 * 32 + lane];
            float p0 = silu_f(fmaf(a0.x + ox, sc.x, sh.x)) * wg.x
                     + silu_f(fmaf(a0.y + oy, sc.y, sh.y)) * wg.y;
            float p1 = silu_f(fmaf(a1.x + ox, sc.x, sh.x)) * wg.x
                     + silu_f(fmaf(a1.y + oy, sc.y, sh.y)) * wg.y;
            #pragma unroll
            for (int off = 16; off; off >>= 1) {
                p0 += __shfl_xor_sync(0xffffffffu, p0, off);
                p1 += __shfl_xor_sync(0xffffffffu, p1, off);
            }
            if (lane == 0) {
                p0 += bgv; p1 += bgv;
                d_graw[j] = p0;     d_graw[j + 1] = p1;
                sg += p0 + p1;
                sg2 = fmaf(p0, p0, sg2);
                sg2 = fmaf(p1, p1, sg2);
            }
        }
        for (; j < r1; j++) {
            int s0 = d_csrc[j];
            float2 a0 = d_A[s0 * 32 + lane];
            float p0 = silu_f(fmaf(a0.x + ox, sc.x, sh.x)) * wg.x
                     + silu_f(fmaf(a0.y + oy, sc.y, sh.y)) * wg.y;
            #pragma unroll
            for (int off = 16; off; off >>= 1)
                p0 += __shfl_xor_sync(0xffffffffu, p0, off);
            if (lane == 0) {
                p0 += bgv;
                d_graw[j] = p0;
                sg += p0;
                sg2 = fmaf(p0, p0, sg2);
            }
        }
    }
    if (lane == 0) {
        atomicAdd(&d_gstats[0], sg);
        atomicAdd(&d_gstats[1], sg2);
    }
}

// ------------- K8: finalize gate BN params -------------
__global__ void k_bng(const float* __restrict__ gg, const float* __restrict__ bgb, float Ef) {
    float mu  = d_gstats[0] / Ef;
    float var = d_gstats[1] / Ef - mu * mu;
    float sc  = gg[0] * rsqrtf(var + BN_EPS);
    d_gparams[0] = sc;
    d_gparams[1] = bgb[0] - mu * sc;
}

// ------------- K9: segment softmax + weighted aggregate -------------
__global__ void k_agg(const float* __restrict__ b1, float* __restrict__ out, int n) {
    int lane = threadIdx.x & 31;
    int wid  = (blockIdx.x * blockDim.x + threadIdx.x) >> 5;
    int nw   = (gridDim.x * blockDim.x) >> 5;
    float2 bias = ((const float2*)b1)[lane];
    float2 sc = d_scale1[lane];
    float2 sh = d_shift1[lane];
    float gsc = d_gparams[0], gsh = d_gparams[1];
    float2* out2 = (float2*)out;
    for (int nd = wid; nd < n; nd += nw) {
        int r0 = d_rowptr[nd], r1 = d_rowptr[nd + 1];
        if (r0 == r1) {
            out2[nd * 32 + lane] = make_float2(0.0f, 0.0f);
            continue;
        }
        // pass 1: g = silu(BN(graw)); store g back; segment max
        float m = -INFINITY;
        for (int j = r0 + lane; j < r1; j += 32) {
            float g = silu_f(fmaf(d_graw[j], gsc, gsh));
            d_graw[j] = g;
            m = fmaxf(m, g);
        }
        #pragma unroll
        for (int off = 16; off; off >>= 1)
            m = fmaxf(m, __shfl_xor_sync(0xffffffffu, m, off));
        __syncwarp();
        // pass 2: e = exp(g - m); store back; sum
        float ssum = 0.f;
        for (int j = r0 + lane; j < r1; j += 32) {
            float e = __expf(d_graw[j] - m);
            d_graw[j] = e;
            ssum += e;
        }
        #pragma unroll
        for (int off = 16; off; off >>= 1)
            ssum += __shfl_xor_sync(0xffffffffu, ssum, off);
        float inv = 1.0f / (ssum + 1e-16f);
        __syncwarp();
        // pass 3: weighted aggregate (uniform per-edge weight, float2 gather)
        float2 bp = d_Bp[nd * 32 + lane];
        float ox = bias.x - bp.x, oy = bias.y - bp.y;
        float acc0 = 0.f, acc1 = 0.f;
        int j = r0;
        for (; j + 2 <= r1; j += 2) {
            int s0 = d_csrc[j], s1 = d_csrc[j + 1];
            float w0 = d_graw[j] * inv, w1 = d_graw[j + 1] * inv;
            float2 a0 = d_A[s0 * 32 + lane];
            float2 a1 = d_A[s1 * 32 + lane];
            acc0 = fmaf(w0, silu_f(fmaf(a0.x + ox, sc.x, sh.x)), acc0);
            acc1 = fmaf(w0, silu_f(fmaf(a0.y + oy, sc.y, sh.y)), acc1);
            acc0 = fmaf(w1, silu_f(fmaf(a1.x + ox, sc.x, sh.x)), acc0);
            acc1 = fmaf(w1, silu_f(fmaf(a1.y + oy, sc.y, sh.y)), acc1);
        }
        for (; j < r1; j++) {
            int s0 = d_csrc[j];
            float w0 = d_graw[j] * inv;
            float2 a0 = d_A[s0 * 32 + lane];
            acc0 = fmaf(w0, silu_f(fmaf(a0.x + ox, sc.x, sh.x)), acc0);
            acc1 = fmaf(w0, silu_f(fmaf(a0.y + oy, sc.y, sh.y)), acc1);
        }
        out2[nd * 32 + lane] = make_float2(acc0, acc1);
    }
}

// ------------- launch -------------
extern "C" void kernel_launch(void* const* d_in, const int* in_sizes, int n_in,
                              void* d_out, int out_size) {
    const float* x   = (const float*)d_in[0];
    const float* pos = (const float*)d_in[1];
    const int*   ei  = (const int*)d_in[2];   // int32 [2, E]
    const float* W1  = (const float*)d_in[3];
    const float* b1  = (const float*)d_in[4];
    const float* g1  = (const float*)d_in[5];
    const float* be1 = (const float*)d_in[6];
    const float* Wg  = (const float*)d_in[7];
    const float* bg  = (const float*)d_in[8];
    const float* gg  = (const float*)d_in[9];
    const float* bgb = (const float*)d_in[10];
    float* out = (float*)d_out;

    int n = in_sizes[0] / INCH;   // 100000
    int e = in_sizes[2] / 2;      // 1600000
    int nb = (n + SCAN_BLK - 1) / SCAN_BLK;

    k_init   <<<256, 256>>>(n);
    k_node   <<<512, 256>>>(x, pos, W1, n);
    k_count  <<<512, 256>>>(ei, e, n);
    k_scanA  <<<nb, SCAN_BLK>>>(n);
    k_scanB  <<<1, 128>>>(nb, n);
    k_scanC  <<<nb, SCAN_BLK>>>(n);
    k_scatter<<<512, 256>>>(ei, e, n);
    k_zstats <<<1024, 256>>>(b1, n);
    k_bn1    <<<1, 64>>>(g1, be1, (float)e);
    k_gate   <<<1024, 256>>>(b1, Wg, bg, n);
    k_bng    <<<1, 1>>>(gg, bgb, (float)e);
    k_agg    <<<1024, 256>>>(b1, out, n);
}

// round 4
// speedup vs baseline: 1.5006x; 1.2284x over previous
#include <cuda_runtime.h>
#include <math.h>

#define NMAXN 100000
#define NMAXE 1600000
#define INCH 61
#define OC 64
#define BN_EPS 1e-5f
#define SCAN_BLK 1024

// ------------- static device scratch (no allocation allowed) -------------
__device__ float2 d_A[NMAXN * 32];    // x@W1[:61] + pos@W1[61:], channel pair (2l, 2l+1)
__device__ float2 d_Bp[NMAXN * 32];   // pos@W1[61:]
__device__ int    d_deg[NMAXN];       // in-degree
__device__ int    d_odeg[NMAXN];      // out-degree
__device__ float  d_V[NMAXN * 3];     // V[n,r] = sum over out-edges of n of pos[dst,r]
__device__ int    d_scanned[NMAXN];
__device__ int    d_bsum[128];
__device__ int    d_rowptr[NMAXN + 1];
__device__ int    d_cursor[NMAXN];
__device__ int    d_csrc[NMAXE];      // src node per CSR slot (grouped by dst)
__device__ float  d_graw[NMAXE];      // gate value per CSR slot (staged: raw -> g -> e)
__device__ float  d_s1[OC];           // sum outdeg*A
__device__ float  d_s2[OC];           // sum indeg*Bp
__device__ float  d_s3[OC];           // sum outdeg*A^2
__device__ float  d_s4[OC];           // sum indeg*(b1-Bp)^2
__device__ float  d_s5[OC];           // sum_e A[s]*Bp[d]  (via rank-3 V)
__device__ float2 d_scale1[32];
__device__ float2 d_shift1[32];
__device__ float  d_gstats[2];
__device__ float  d_gparams[2];

// silu via single-MUFU tanh.approx:  silu(t) = u*(1+tanh(u)), u = t/2
__device__ __forceinline__ float silu_f(float t) {
    float u = 0.5f * t;
    float v;
    asm("tanh.approx.f32 %0, %1;" : "=f"(v) : "f"(u));
    return fmaf(u, v, u);
}

// ------------- K0: zero counters / stats -------------
__global__ void k_init(int n) {
    int i = blockIdx.x * blockDim.x + threadIdx.x;
    int st = gridDim.x * blockDim.x;
    for (int t = i; t < n; t += st) {
        d_deg[t] = 0;
        d_odeg[t] = 0;
        d_V[t] = 0.f;
        d_V[t + NMAXN] = 0.f;       // flat zeroing: 3n handled below
        d_V[t + 2 * NMAXN] = 0.f;
    }
    if (i < OC) { d_s1[i] = 0.f; d_s2[i] = 0.f; d_s3[i] = 0.f; d_s4[i] = 0.f; d_s5[i] = 0.f; }
    if (i < 2)  { d_gstats[i] = 0.f; }
}

// ------------- K1: per-node transform -------------
__global__ void k_node(const float* __restrict__ x, const float* __restrict__ pos,
                       const float* __restrict__ W1, int n) {
    __shared__ float2 sW[64 * 32];
    const float2* W2 = (const float2*)W1;
    for (int i = threadIdx.x; i < 64 * 32; i += blockDim.x) sW[i] = W2[i];
    __syncthreads();
    int lane = threadIdx.x & 31;
    int wid  = (blockIdx.x * blockDim.x + threadIdx.x) >> 5;
    int nw   = (gridDim.x * blockDim.x) >> 5;
    for (int nd = wid; nd < n; nd += nw) {
        float a0 = 0.f, a1 = 0.f, b0 = 0.f, b1v = 0.f;
        const float* xr = x + (long long)nd * INCH;
        #pragma unroll
        for (int k = 0; k < INCH; k++) {
            float xv = __ldg(xr + k);
            float2 w = sW[k * 32 + lane];
            a0 = fmaf(xv, w.x, a0);
            a1 = fmaf(xv, w.y, a1);
        }
        const float* pr = pos + (long long)nd * 3;
        #pragma unroll
        for (int k = 0; k < 3; k++) {
            float pv = __ldg(pr + k);
            float2 w = sW[(INCH + k) * 32 + lane];
            b0  = fmaf(pv, w.x, b0);
            b1v = fmaf(pv, w.y, b1v);
        }
        d_A[nd * 32 + lane]  = make_float2(a0 + b0, a1 + b1v);
        d_Bp[nd * 32 + lane] = make_float2(b0, b1v);
    }
}

// ------------- K2: degree histograms -------------
__global__ void k_count(const int* __restrict__ ei, int e, int n) {
    int i = blockIdx.x * blockDim.x + threadIdx.x;
    int st = gridDim.x * blockDim.x;
    for (; i < e; i += st) {
        unsigned s = (unsigned)ei[i];
        unsigned d = (unsigned)ei[e + i];
        if (d < (unsigned)n) atomicAdd(&d_deg[d], 1);
        if (s < (unsigned)n) atomicAdd(&d_odeg[s], 1);
    }
}

// ------------- K3a: per-block inclusive scan of deg -------------
__global__ void k_scanA(int n) {
    __shared__ int sh[32];
    int t = threadIdx.x, lane = t & 31, w = t >> 5;
    int idx = blockIdx.x * SCAN_BLK + t;
    int v = (idx < n) ? d_deg[idx] : 0;
    int xv = v;
    #pragma unroll
    for (int off = 1; off < 32; off <<= 1) {
        int y = __shfl_up_sync(0xffffffffu, xv, off);
        if (lane >= off) xv += y;
    }
    if (lane == 31) sh[w] = xv;
    __syncthreads();
    if (w == 0) {
        int y2 = sh[lane];
        #pragma unroll
        for (int off = 1; off < 32; off <<= 1) {
            int z = __shfl_up_sync(0xffffffffu, y2, off);
            if (lane >= off) y2 += z;
        }
        sh[lane] = y2;
    }
    __syncthreads();
    int incl = xv + ((w > 0) ? sh[w - 1] : 0);
    if (idx < n) d_scanned[idx] = incl;
    if (t == SCAN_BLK - 1) d_bsum[blockIdx.x] = incl;
}

// ------------- K3b: exclusive scan of block sums -------------
__global__ void k_scanB(int nb, int n) {
    __shared__ int sw[4];
    int t = threadIdx.x, lane = t & 31, w = t >> 5;
    int v = (t < nb) ? d_bsum[t] : 0;
    int xv = v;
    #pragma unroll
    for (int off = 1; off < 32; off <<= 1) {
        int y = __shfl_up_sync(0xffffffffu, xv, off);
        if (lane >= off) xv += y;
    }
    if (lane == 31) sw[w] = xv;
    __syncthreads();
    if (t == 0) {
        int run = 0;
        #pragma unroll
        for (int i = 0; i < 4; i++) { int tmp = sw[i]; sw[i] = run; run += tmp; }
    }
    __syncthreads();
    int incl = xv + sw[w];
    if (t < nb) d_bsum[t] = incl - v;
    if (t == nb - 1) d_rowptr[n] = incl;
}

// ------------- K3c: finalize rowptr/cursor -------------
__global__ void k_scanC(int n) {
    int idx = blockIdx.x * SCAN_BLK + threadIdx.x;
    if (idx < n) {
        int ex = d_scanned[idx] - d_deg[idx] + d_bsum[blockIdx.x];
        d_rowptr[idx] = ex;
        d_cursor[idx] = ex;
    }
}

// ------------- K4: scatter src ids into CSR slots + accumulate V[s] += pos[d] -------------
__global__ void k_scatter(const int* __restrict__ ei, const float* __restrict__ pos,
                          int e, int n) {
    int i = blockIdx.x * blockDim.x + threadIdx.x;
    int st = gridDim.x * blockDim.x;
    for (; i < e; i += st) {
        unsigned s = (unsigned)ei[i];
        unsigned d = (unsigned)ei[e + i];
        if (s >= (unsigned)n || d >= (unsigned)n) continue;
        int p = atomicAdd(&d_cursor[d], 1);
        d_csrc[p] = (int)s;
        const float* pd = pos + (size_t)d * 3;
        atomicAdd(&d_V[s * 3 + 0], pd[0]);
        atomicAdd(&d_V[s * 3 + 1], pd[1]);
        atomicAdd(&d_V[s * 3 + 2], pd[2]);
    }
}

// ------------- K5: node-level BN1 stats (zstats decomposed, no edge gather) -------------
__global__ void k_zstats(const float* __restrict__ b1, const float* __restrict__ W1, int n) {
    int lane = threadIdx.x & 31;
    int wid  = (blockIdx.x * blockDim.x + threadIdx.x) >> 5;
    int nw   = (gridDim.x * blockDim.x) >> 5;
    float2 bias = ((const float2*)b1)[lane];
    float2 w61 = ((const float2*)(W1 + 61 * OC))[lane];
    float2 w62 = ((const float2*)(W1 + 62 * OC))[lane];
    float2 w63 = ((const float2*)(W1 + 63 * OC))[lane];
    float s1x = 0.f, s1y = 0.f, s2x = 0.f, s2y = 0.f, s3x = 0.f, s3y = 0.f;
    float s4x = 0.f, s4y = 0.f, s5x = 0.f, s5y = 0.f;
    for (int nd = wid; nd < n; nd += nw) {
        float od = (float)d_odeg[nd];
        float id = (float)d_deg[nd];
        float2 a  = d_A[nd * 32 + lane];
        float2 bp = d_Bp[nd * 32 + lane];
        float v0 = d_V[nd * 3 + 0], v1 = d_V[nd * 3 + 1], v2 = d_V[nd * 3 + 2];
        s1x = fmaf(od, a.x, s1x);          s1y = fmaf(od, a.y, s1y);
        s2x = fmaf(id, bp.x, s2x);         s2y = fmaf(id, bp.y, s2y);
        s3x = fmaf(od * a.x, a.x, s3x);    s3y = fmaf(od * a.y, a.y, s3y);
        float ox = bias.x - bp.x, oy = bias.y - bp.y;
        s4x = fmaf(id * ox, ox, s4x);      s4y = fmaf(id * oy, oy, s4y);
        float bvx = v0 * w61.x + v1 * w62.x + v2 * w63.x;
        float bvy = v0 * w61.y + v1 * w62.y + v2 * w63.y;
        s5x = fmaf(a.x, bvx, s5x);         s5y = fmaf(a.y, bvy, s5y);
    }
    atomicAdd(&d_s1[2 * lane], s1x);     atomicAdd(&d_s1[2 * lane + 1], s1y);
    atomicAdd(&d_s2[2 * lane], s2x);     atomicAdd(&d_s2[2 * lane + 1], s2y);
    atomicAdd(&d_s3[2 * lane], s3x);     atomicAdd(&d_s3[2 * lane + 1], s3y);
    atomicAdd(&d_s4[2 * lane], s4x);     atomicAdd(&d_s4[2 * lane + 1], s4y);
    atomicAdd(&d_s5[2 * lane], s5x);     atomicAdd(&d_s5[2 * lane + 1], s5y);
}

// ------------- K6: finalize BN1 params -------------
// sum z  = s1 + E*b1 - s2
// sum z2 = s3 + s4 + 2*(b1*s1 - s5)
__global__ void k_bn1(const float* __restrict__ g1, const float* __restrict__ be1,
                      const float* __restrict__ b1, float Ef) {
    int c = threadIdx.x;
    float bc = b1[c];
    float sumz  = d_s1[c] + Ef * bc - d_s2[c];
    float sumz2 = d_s3[c] + d_s4[c] + 2.0f * (bc * d_s1[c] - d_s5[c]);
    float mu  = sumz / Ef;
    float var = sumz2 / Ef - mu * mu;
    float sc  = g1[c] * rsqrtf(var + BN_EPS);
    ((float*)d_scale1)[c] = sc;
    ((float*)d_shift1)[c] = be1[c] - mu * sc;
}

// ------------- K7: gate_raw per edge + gate stats -------------
__global__ void k_gate(const float* __restrict__ b1, const float* __restrict__ Wg,
                       const float* __restrict__ bg, int n) {
    int lane = threadIdx.x & 31;
    int wid  = (blockIdx.x * blockDim.x + threadIdx.x) >> 5;
    int nw   = (gridDim.x * blockDim.x) >> 5;
    float2 bias = ((const float2*)b1)[lane];
    float2 sc = d_scale1[lane];
    float2 sh = d_shift1[lane];
    float2 wg = ((const float2*)Wg)[lane];
    float bgv = bg[0];
    float sg = 0.f, sg2 = 0.f;
    for (int nd = wid; nd < n; nd += nw) {
        int r0 = d_rowptr[nd], r1 = d_rowptr[nd + 1];
        if (r0 == r1) continue;
        float2 bp = d_Bp[nd * 32 + lane];
        float ox = bias.x - bp.x, oy = bias.y - bp.y;
        int j = r0;
        for (; j + 2 <= r1; j += 2) {
            int s0 = d_csrc[j], s1 = d_csrc[j + 1];
            float2 a0 = d_A[s0 * 32 + lane];
            float2 a1 = d_A[s1 * 32 + lane];
            float p0 = silu_f(fmaf(a0.x + ox, sc.x, sh.x)) * wg.x
                     + silu_f(fmaf(a0.y + oy, sc.y, sh.y)) * wg.y;
            float p1 = silu_f(fmaf(a1.x + ox, sc.x, sh.x)) * wg.x
                     + silu_f(fmaf(a1.y + oy, sc.y, sh.y)) * wg.y;
            #pragma unroll
            for (int off = 16; off; off >>= 1) {
                p0 += __shfl_xor_sync(0xffffffffu, p0, off);
                p1 += __shfl_xor_sync(0xffffffffu, p1, off);
            }
            if (lane == 0) {
                p0 += bgv; p1 += bgv;
                d_graw[j] = p0;     d_graw[j + 1] = p1;
                sg += p0 + p1;
                sg2 = fmaf(p0, p0, sg2);
                sg2 = fmaf(p1, p1, sg2);
            }
        }
        for (; j < r1; j++) {
            int s0 = d_csrc[j];
            float2 a0 = d_A[s0 * 32 + lane];
            float p0 = silu_f(fmaf(a0.x + ox, sc.x, sh.x)) * wg.x
                     + silu_f(fmaf(a0.y + oy, sc.y, sh.y)) * wg.y;
            #pragma unroll
            for (int off = 16; off; off >>= 1)
                p0 += __shfl_xor_sync(0xffffffffu, p0, off);
            if (lane == 0) {
                p0 += bgv;
                d_graw[j] = p0;
                sg += p0;
                sg2 = fmaf(p0, p0, sg2);
            }
        }
    }
    if (lane == 0) {
        atomicAdd(&d_gstats[0], sg);
        atomicAdd(&d_gstats[1], sg2);
    }
}

// ------------- K8: finalize gate BN params -------------
__global__ void k_bng(const float* __restrict__ gg, const float* __restrict__ bgb, float Ef) {
    float mu  = d_gstats[0] / Ef;
    float var = d_gstats[1] / Ef - mu * mu;
    float sc  = gg[0] * rsqrtf(var + BN_EPS);
    d_gparams[0] = sc;
    d_gparams[1] = bgb[0] - mu * sc;
}

// ------------- K9: segment softmax + weighted aggregate -------------
__global__ void k_agg(const float* __restrict__ b1, float* __restrict__ out, int n) {
    int lane = threadIdx.x & 31;
    int wid  = (blockIdx.x * blockDim.x + threadIdx.x) >> 5;
    int nw   = (gridDim.x * blockDim.x) >> 5;
    float2 bias = ((const float2*)b1)[lane];
    float2 sc = d_scale1[lane];
    float2 sh = d_shift1[lane];
    float gsc = d_gparams[0], gsh = d_gparams[1];
    float2* out2 = (float2*)out;
    for (int nd = wid; nd < n; nd += nw) {
        int r0 = d_rowptr[nd], r1 = d_rowptr[nd + 1];
        if (r0 == r1) {
            out2[nd * 32 + lane] = make_float2(0.0f, 0.0f);
            continue;
        }
        // pass 1: g = silu(BN(graw)); store g back; segment max
        float m = -INFINITY;
        for (int j = r0 + lane; j < r1; j += 32) {
            float g = silu_f(fmaf(d_graw[j], gsc, gsh));
            d_graw[j] = g;
            m = fmaxf(m, g);
        }
        #pragma unroll
        for (int off = 16; off; off >>= 1)
            m = fmaxf(m, __shfl_xor_sync(0xffffffffu, m, off));
        __syncwarp();
        // pass 2: e = exp(g - m); store back; sum
        float ssum = 0.f;
        for (int j = r0 + lane; j < r1; j += 32) {
            float e = __expf(d_graw[j] - m);
            d_graw[j] = e;
            ssum += e;
        }
        #pragma unroll
        for (int off = 16; off; off >>= 1)
            ssum += __shfl_xor_sync(0xffffffffu, ssum, off);
        float inv = 1.0f / (ssum + 1e-16f);
        __syncwarp();
        // pass 3: weighted aggregate
        float2 bp = d_Bp[nd * 32 + lane];
        float ox = bias.x - bp.x, oy = bias.y - bp.y;
        float acc0 = 0.f, acc1 = 0.f;
        int j = r0;
        for (; j + 2 <= r1; j += 2) {
            int s0 = d_csrc[j], s1 = d_csrc[j + 1];
            float w0 = d_graw[j] * inv, w1 = d_graw[j + 1] * inv;
            float2 a0 = d_A[s0 * 32 + lane];
            float2 a1 = d_A[s1 * 32 + lane];
            acc0 = fmaf(w0, silu_f(fmaf(a0.x + ox, sc.x, sh.x)), acc0);
            acc1 = fmaf(w0, silu_f(fmaf(a0.y + oy, sc.y, sh.y)), acc1);
            acc0 = fmaf(w1, silu_f(fmaf(a1.x + ox, sc.x, sh.x)), acc0);
            acc1 = fmaf(w1, silu_f(fmaf(a1.y + oy, sc.y, sh.y)), acc1);
        }
        for (; j < r1; j++) {
            int s0 = d_csrc[j];
            float w0 = d_graw[j] * inv;
            float2 a0 = d_A[s0 * 32 + lane];
            acc0 = fmaf(w0, silu_f(fmaf(a0.x + ox, sc.x, sh.x)), acc0);
            acc1 = fmaf(w0, silu_f(fmaf(a0.y + oy, sc.y, sh.y)), acc1);
        }
        out2[nd * 32 + lane] = make_float2(acc0, acc1);
    }
}

// ------------- launch -------------
extern "C" void kernel_launch(void* const* d_in, const int* in_sizes, int n_in,
                              void* d_out, int out_size) {
    const float* x   = (const float*)d_in[0];
    const float* pos = (const float*)d_in[1];
    const int*   ei  = (const int*)d_in[2];   // int32 [2, E]
    const float* W1  = (const float*)d_in[3];
    const float* b1  = (const float*)d_in[4];
    const float* g1  = (const float*)d_in[5];
    const float* be1 = (const float*)d_in[6];
    const float* Wg  = (const float*)d_in[7];
    const float* bg  = (const float*)d_in[8];
    const float* gg  = (const float*)d_in[9];
    const float* bgb = (const float*)d_in[10];
    float* out = (float*)d_out;

    int n = in_sizes[0] / INCH;   // 100000
    int e = in_sizes[2] / 2;      // 1600000
    int nb = (n + SCAN_BLK - 1) / SCAN_BLK;

    k_init   <<<256, 256>>>(n);
    k_node   <<<512, 256>>>(x, pos, W1, n);
    k_count  <<<512, 256>>>(ei, e, n);
    k_scanA  <<<nb, SCAN_BLK>>>(n);
    k_scanB  <<<1, 128>>>(nb, n);
    k_scanC  <<<nb, SCAN_BLK>>>(n);
    k_scatter<<<512, 256>>>(ei, pos, e, n);
    k_zstats <<<256, 256>>>(b1, W1, n);
    k_bn1    <<<1, 64>>>(g1, be1, b1, (float)e);
    k_gate   <<<1024, 256>>>(b1, Wg, bg, n);
    k_bng    <<<1, 1>>>(gg, bgb, (float)e);
    k_agg    <<<1024, 256>>>(b1, out, n);
}

// round 5
// speedup vs baseline: 1.6937x; 1.1287x over previous
#include <cuda_runtime.h>
#include <math.h>

#define NMAXN 100000
#define NMAXE 1600000
#define INCH 61
#define OC 64
#define BN_EPS 1e-5f
#define SCAN_BLK 1024

// ------------- static device scratch (no allocation allowed) -------------
__device__ float4 d_A4[NMAXN * 16];   // per node: 64 ch; float4 g = channels 4g..4g+3
__device__ float4 d_Bp4[NMAXN * 16];  // pos @ W1[61:64]
__device__ int    d_deg[NMAXN];       // in-degree
__device__ int    d_odeg[NMAXN];      // out-degree
__device__ float  d_V[NMAXN * 3];     // V[n,r] = sum over out-edges of n of pos[dst,r]
__device__ int    d_scanned[NMAXN];
__device__ int    d_bsum[128];
__device__ int    d_rowptr[NMAXN + 1];
__device__ int    d_cursor[NMAXN];
__device__ int    d_csrc[NMAXE];      // src node per CSR slot (grouped by dst)
__device__ float  d_graw[NMAXE];      // gate value per CSR slot (staged: raw -> e)
__device__ float  d_s1[OC];
__device__ float  d_s2[OC];
__device__ float  d_s3[OC];
__device__ float  d_s4[OC];
__device__ float  d_s5[OC];
__device__ float4 d_scale1[16];
__device__ float4 d_shift1[16];
__device__ float  d_gstats[2];
__device__ float  d_gparams[2];

// silu via single-MUFU tanh.approx:  silu(t) = u*(1+tanh(u)), u = t/2
__device__ __forceinline__ float silu_f(float t) {
    float u = 0.5f * t;
    float v;
    asm("tanh.approx.f32 %0, %1;" : "=f"(v) : "f"(u));
    return fmaf(u, v, u);
}

// ------------- K0: zero counters / stats -------------
__global__ void k_init(int n) {
    int i = blockIdx.x * blockDim.x + threadIdx.x;
    int st = gridDim.x * blockDim.x;
    for (int t = i; t < n; t += st) { d_deg[t] = 0; d_odeg[t] = 0; }
    for (int t = i; t < 3 * n; t += st) d_V[t] = 0.f;
    if (i < OC) { d_s1[i] = 0.f; d_s2[i] = 0.f; d_s3[i] = 0.f; d_s4[i] = 0.f; d_s5[i] = 0.f; }
    if (i < 2)  { d_gstats[i] = 0.f; }
}

// ------------- K1: per-node transform -------------
__global__ void k_node(const float* __restrict__ x, const float* __restrict__ pos,
                       const float* __restrict__ W1, int n) {
    __shared__ float2 sW[64 * 32];
    const float2* W2 = (const float2*)W1;
    for (int i = threadIdx.x; i < 64 * 32; i += blockDim.x) sW[i] = W2[i];
    __syncthreads();
    int lane = threadIdx.x & 31;
    int wid  = (blockIdx.x * blockDim.x + threadIdx.x) >> 5;
    int nw   = (gridDim.x * blockDim.x) >> 5;
    float2* A2  = (float2*)d_A4;
    float2* Bp2 = (float2*)d_Bp4;
    for (int nd = wid; nd < n; nd += nw) {
        float a0 = 0.f, a1 = 0.f, b0 = 0.f, b1v = 0.f;
        const float* xr = x + (long long)nd * INCH;
        #pragma unroll
        for (int k = 0; k < INCH; k++) {
            float xv = __ldg(xr + k);
            float2 w = sW[k * 32 + lane];
            a0 = fmaf(xv, w.x, a0);
            a1 = fmaf(xv, w.y, a1);
        }
        const float* pr = pos + (long long)nd * 3;
        #pragma unroll
        for (int k = 0; k < 3; k++) {
            float pv = __ldg(pr + k);
            float2 w = sW[(INCH + k) * 32 + lane];
            b0  = fmaf(pv, w.x, b0);
            b1v = fmaf(pv, w.y, b1v);
        }
        A2[nd * 32 + lane]  = make_float2(a0 + b0, a1 + b1v);
        Bp2[nd * 32 + lane] = make_float2(b0, b1v);
    }
}

// ------------- K2: degree histograms -------------
__global__ void k_count(const int* __restrict__ ei, int e, int n) {
    int i = blockIdx.x * blockDim.x + threadIdx.x;
    int st = gridDim.x * blockDim.x;
    for (; i < e; i += st) {
        unsigned s = (unsigned)ei[i];
        unsigned d = (unsigned)ei[e + i];
        if (d < (unsigned)n) atomicAdd(&d_deg[d], 1);
        if (s < (unsigned)n) atomicAdd(&d_odeg[s], 1);
    }
}

// ------------- K3a: per-block inclusive scan of deg -------------
__global__ void k_scanA(int n) {
    __shared__ int sh[32];
    int t = threadIdx.x, lane = t & 31, w = t >> 5;
    int idx = blockIdx.x * SCAN_BLK + t;
    int v = (idx < n) ? d_deg[idx] : 0;
    int xv = v;
    #pragma unroll
    for (int off = 1; off < 32; off <<= 1) {
        int y = __shfl_up_sync(0xffffffffu, xv, off);
        if (lane >= off) xv += y;
    }
    if (lane == 31) sh[w] = xv;
    __syncthreads();
    if (w == 0) {
        int y2 = sh[lane];
        #pragma unroll
        for (int off = 1; off < 32; off <<= 1) {
            int z = __shfl_up_sync(0xffffffffu, y2, off);
            if (lane >= off) y2 += z;
        }
        sh[lane] = y2;
    }
    __syncthreads();
    int incl = xv + ((w > 0) ? sh[w - 1] : 0);
    if (idx < n) d_scanned[idx] = incl;
    if (t == SCAN_BLK - 1) d_bsum[blockIdx.x] = incl;
}

// ------------- K3b: exclusive scan of block sums -------------
__global__ void k_scanB(int nb, int n) {
    __shared__ int sw[4];
    int t = threadIdx.x, lane = t & 31, w = t >> 5;
    int v = (t < nb) ? d_bsum[t] : 0;
    int xv = v;
    #pragma unroll
    for (int off = 1; off < 32; off <<= 1) {
        int y = __shfl_up_sync(0xffffffffu, xv, off);
        if (lane >= off) xv += y;
    }
    if (lane == 31) sw[w] = xv;
    __syncthreads();
    if (t == 0) {
        int run = 0;
        #pragma unroll
        for (int i = 0; i < 4; i++) { int tmp = sw[i]; sw[i] = run; run += tmp; }
    }
    __syncthreads();
    int incl = xv + sw[w];
    if (t < nb) d_bsum[t] = incl - v;
    if (t == nb - 1) d_rowptr[n] = incl;
}

// ------------- K3c: finalize rowptr/cursor -------------
__global__ void k_scanC(int n) {
    int idx = blockIdx.x * SCAN_BLK + threadIdx.x;
    if (idx < n) {
        int ex = d_scanned[idx] - d_deg[idx] + d_bsum[blockIdx.x];
        d_rowptr[idx] = ex;
        d_cursor[idx] = ex;
    }
}

// ------------- K4: scatter src ids into CSR slots + accumulate V[s] += pos[d] -------------
__global__ void k_scatter(const int* __restrict__ ei, const float* __restrict__ pos,
                          int e, int n) {
    int i = blockIdx.x * blockDim.x + threadIdx.x;
    int st = gridDim.x * blockDim.x;
    for (; i < e; i += st) {
        unsigned s = (unsigned)ei[i];
        unsigned d = (unsigned)ei[e + i];
        if (s >= (unsigned)n || d >= (unsigned)n) continue;
        int p = atomicAdd(&d_cursor[d], 1);
        d_csrc[p] = (int)s;
        const float* pd = pos + (size_t)d * 3;
        atomicAdd(&d_V[s * 3 + 0], pd[0]);
        atomicAdd(&d_V[s * 3 + 1], pd[1]);
        atomicAdd(&d_V[s * 3 + 2], pd[2]);
    }
}

// ------------- K5: node-level BN1 stats -------------
__global__ void k_zstats(const float* __restrict__ b1, const float* __restrict__ W1, int n) {
    int lane = threadIdx.x & 31;
    int wid  = (blockIdx.x * blockDim.x + threadIdx.x) >> 5;
    int nw   = (gridDim.x * blockDim.x) >> 5;
    const float2* A2  = (const float2*)d_A4;
    const float2* Bp2 = (const float2*)d_Bp4;
    float2 bias = ((const float2*)b1)[lane];
    float2 w61 = ((const float2*)(W1 + 61 * OC))[lane];
    float2 w62 = ((const float2*)(W1 + 62 * OC))[lane];
    float2 w63 = ((const float2*)(W1 + 63 * OC))[lane];
    float s1x = 0.f, s1y = 0.f, s2x = 0.f, s2y = 0.f, s3x = 0.f, s3y = 0.f;
    float s4x = 0.f, s4y = 0.f, s5x = 0.f, s5y = 0.f;
    for (int nd = wid; nd < n; nd += nw) {
        float od = (float)d_odeg[nd];
        float id = (float)d_deg[nd];
        float2 a  = A2[nd * 32 + lane];
        float2 bp = Bp2[nd * 32 + lane];
        float v0 = d_V[nd * 3 + 0], v1 = d_V[nd * 3 + 1], v2 = d_V[nd * 3 + 2];
        s1x = fmaf(od, a.x, s1x);          s1y = fmaf(od, a.y, s1y);
        s2x = fmaf(id, bp.x, s2x);         s2y = fmaf(id, bp.y, s2y);
        s3x = fmaf(od * a.x, a.x, s3x);    s3y = fmaf(od * a.y, a.y, s3y);
        float ox = bias.x - bp.x, oy = bias.y - bp.y;
        s4x = fmaf(id * ox, ox, s4x);      s4y = fmaf(id * oy, oy, s4y);
        float bvx = v0 * w61.x + v1 * w62.x + v2 * w63.x;
        float bvy = v0 * w61.y + v1 * w62.y + v2 * w63.y;
        s5x = fmaf(a.x, bvx, s5x);         s5y = fmaf(a.y, bvy, s5y);
    }
    atomicAdd(&d_s1[2 * lane], s1x);     atomicAdd(&d_s1[2 * lane + 1], s1y);
    atomicAdd(&d_s2[2 * lane], s2x);     atomicAdd(&d_s2[2 * lane + 1], s2y);
    atomicAdd(&d_s3[2 * lane], s3x);     atomicAdd(&d_s3[2 * lane + 1], s3y);
    atomicAdd(&d_s4[2 * lane], s4x);     atomicAdd(&d_s4[2 * lane + 1], s4y);
    atomicAdd(&d_s5[2 * lane], s5x);     atomicAdd(&d_s5[2 * lane + 1], s5y);
}

// ------------- K6: finalize BN1 params -------------
__global__ void k_bn1(const float* __restrict__ g1, const float* __restrict__ be1,
                      const float* __restrict__ b1, float Ef) {
    int c = threadIdx.x;
    float bc = b1[c];
    float sumz  = d_s1[c] + Ef * bc - d_s2[c];
    float sumz2 = d_s3[c] + d_s4[c] + 2.0f * (bc * d_s1[c] - d_s5[c]);
    float mu  = sumz / Ef;
    float var = sumz2 / Ef - mu * mu;
    float sc  = g1[c] * rsqrtf(var + BN_EPS);
    ((float*)d_scale1)[c] = sc;
    ((float*)d_shift1)[c] = be1[c] - mu * sc;
}

// ------------- K7: gate_raw per edge + gate stats (half-warp per edge, float4) -------------
__global__ void k_gate(const float* __restrict__ b1, const float* __restrict__ Wg,
                       const float* __restrict__ bg, int n) {
    int lane = threadIdx.x & 31;
    int half = lane >> 4;        // 0 or 1
    int hl   = lane & 15;        // channel quad index
    int wid  = (blockIdx.x * blockDim.x + threadIdx.x) >> 5;
    int nw   = (gridDim.x * blockDim.x) >> 5;
    float4 bias = ((const float4*)b1)[hl];
    float4 sc = d_scale1[hl];
    float4 sh = d_shift1[hl];
    float4 wg = ((const float4*)Wg)[hl];
    float bgv = bg[0];
    float sg = 0.f, sg2 = 0.f;
    for (int nd = wid; nd < n; nd += nw) {
        int r0 = d_rowptr[nd], r1 = d_rowptr[nd + 1];
        if (r0 == r1) continue;
        float4 bp = d_Bp4[nd * 16 + hl];
        float ox = bias.x - bp.x, oy = bias.y - bp.y;
        float oz = bias.z - bp.z, ow = bias.w - bp.w;
        int j = r0;
        // main: 4 edges per iteration, 2 per half-warp
        for (; j + 4 <= r1; j += 4) {
            int sa = d_csrc[j + half];
            int sb = d_csrc[j + 2 + half];
            float4 aa = d_A4[sa * 16 + hl];
            float4 ab = d_A4[sb * 16 + hl];
            float qa = silu_f(fmaf(aa.x + ox, sc.x, sh.x)) * wg.x
                     + silu_f(fmaf(aa.y + oy, sc.y, sh.y)) * wg.y
                     + silu_f(fmaf(aa.z + oz, sc.z, sh.z)) * wg.z
                     + silu_f(fmaf(aa.w + ow, sc.w, sh.w)) * wg.w;
            float qb = silu_f(fmaf(ab.x + ox, sc.x, sh.x)) * wg.x
                     + silu_f(fmaf(ab.y + oy, sc.y, sh.y)) * wg.y
                     + silu_f(fmaf(ab.z + oz, sc.z, sh.z)) * wg.z
                     + silu_f(fmaf(ab.w + ow, sc.w, sh.w)) * wg.w;
            #pragma unroll
            for (int off = 8; off; off >>= 1) {
                qa += __shfl_xor_sync(0xffffffffu, qa, off);
                qb += __shfl_xor_sync(0xffffffffu, qb, off);
            }
            if (hl == 0) {
                float pa = qa + bgv, pb = qb + bgv;
                d_graw[j + half] = pa;
                d_graw[j + 2 + half] = pb;
                sg += pa + pb;
                sg2 = fmaf(pa, pa, sg2);
                sg2 = fmaf(pb, pb, sg2);
            }
        }
        // tail: 1 edge at a time; both halves cover all 64 channels, 4-round reduce
        for (; j < r1; j++) {
            int s0 = d_csrc[j];
            float4 a0 = d_A4[s0 * 16 + hl];
            float q = silu_f(fmaf(a0.x + ox, sc.x, sh.x)) * wg.x
                    + silu_f(fmaf(a0.y + oy, sc.y, sh.y)) * wg.y
                    + silu_f(fmaf(a0.z + oz, sc.z, sh.z)) * wg.z
                    + silu_f(fmaf(a0.w + ow, sc.w, sh.w)) * wg.w;
            #pragma unroll
            for (int off = 8; off; off >>= 1)
                q += __shfl_xor_sync(0xffffffffu, q, off);
            if (lane == 0) {
                float p = q + bgv;
                d_graw[j] = p;
                sg += p;
                sg2 = fmaf(p, p, sg2);
            }
        }
    }
    // combine the two half-leaders (lanes 0 and 16)
    sg  += __shfl_xor_sync(0xffffffffu, sg, 16);
    sg2 += __shfl_xor_sync(0xffffffffu, sg2, 16);
    if (lane == 0) {
        atomicAdd(&d_gstats[0], sg);
        atomicAdd(&d_gstats[1], sg2);
    }
}

// ------------- K8: finalize gate BN params -------------
__global__ void k_bng(const float* __restrict__ gg, const float* __restrict__ bgb, float Ef) {
    float mu  = d_gstats[0] / Ef;
    float var = d_gstats[1] / Ef - mu * mu;
    float sc  = gg[0] * rsqrtf(var + BN_EPS);
    d_gparams[0] = sc;
    d_gparams[1] = bgb[0] - mu * sc;
}

// ------------- K9: softmax (no max-shift; silu output bounded) + weighted aggregate -------------
__global__ void k_agg(const float* __restrict__ b1, float* __restrict__ out, int n) {
    int lane = threadIdx.x & 31;
    int half = lane >> 4;
    int hl   = lane & 15;
    int wid  = (blockIdx.x * blockDim.x + threadIdx.x) >> 5;
    int nw   = (gridDim.x * blockDim.x) >> 5;
    float4 bias = ((const float4*)b1)[hl];
    float4 sc = d_scale1[hl];
    float4 sh = d_shift1[hl];
    float gsc = d_gparams[0], gsh = d_gparams[1];
    float4* out4 = (float4*)out;
    for (int nd = wid; nd < n; nd += nw) {
        int r0 = d_rowptr[nd], r1 = d_rowptr[nd + 1];
        if (r0 == r1) {
            if (half == 0) out4[nd * 16 + hl] = make_float4(0.f, 0.f, 0.f, 0.f);
            continue;
        }
        // pass A: e = exp(silu(BN(p))); store e; sum
        float ssum = 0.f;
        for (int j = r0 + lane; j < r1; j += 32) {
            float g = silu_f(fmaf(d_graw[j], gsc, gsh));
            float e = __expf(g);
            d_graw[j] = e;
            ssum += e;
        }
        #pragma unroll
        for (int off = 16; off; off >>= 1)
            ssum += __shfl_xor_sync(0xffffffffu, ssum, off);
        float inv = 1.0f / (ssum + 1e-16f);
        __syncwarp();
        // pass B: weighted aggregate, 4 edges per iteration (2 per half)
        float4 bp = d_Bp4[nd * 16 + hl];
        float ox = bias.x - bp.x, oy = bias.y - bp.y;
        float oz = bias.z - bp.z, ow = bias.w - bp.w;
        float ax = 0.f, ay = 0.f, az = 0.f, aw = 0.f;
        int j = r0;
        for (; j + 4 <= r1; j += 4) {
            int sa = d_csrc[j + half];
            int sb = d_csrc[j + 2 + half];
            float wa = d_graw[j + half] * inv;
            float wb = d_graw[j + 2 + half] * inv;
            float4 aa = d_A4[sa * 16 + hl];
            float4 ab = d_A4[sb * 16 + hl];
            ax = fmaf(wa, silu_f(fmaf(aa.x + ox, sc.x, sh.x)), ax);
            ay = fmaf(wa, silu_f(fmaf(aa.y + oy, sc.y, sh.y)), ay);
            az = fmaf(wa, silu_f(fmaf(aa.z + oz, sc.z, sh.z)), az);
            aw = fmaf(wa, silu_f(fmaf(aa.w + ow, sc.w, sh.w)), aw);
            ax = fmaf(wb, silu_f(fmaf(ab.x + ox, sc.x, sh.x)), ax);
            ay = fmaf(wb, silu_f(fmaf(ab.y + oy, sc.y, sh.y)), ay);
            az = fmaf(wb, silu_f(fmaf(ab.z + oz, sc.z, sh.z)), az);
            aw = fmaf(wb, silu_f(fmaf(ab.w + ow, sc.w, sh.w)), aw);
        }
        for (; j < r1; j++) {
            int s0 = d_csrc[j];
            float w0 = (half == 0) ? d_graw[j] * inv : 0.0f;  // avoid double count
            float4 a0 = d_A4[s0 * 16 + hl];
            ax = fmaf(w0, silu_f(fmaf(a0.x + ox, sc.x, sh.x)), ax);
            ay = fmaf(w0, silu_f(fmaf(a0.y + oy, sc.y, sh.y)), ay);
            az = fmaf(w0, silu_f(fmaf(a0.z + oz, sc.z, sh.z)), az);
            aw = fmaf(w0, silu_f(fmaf(a0.w + ow, sc.w, sh.w)), aw);
        }
        // merge the two halves' edge subsets
        ax += __shfl_xor_sync(0xffffffffu, ax, 16);
        ay += __shfl_xor_sync(0xffffffffu, ay, 16);
        az += __shfl_xor_sync(0xffffffffu, az, 16);
        aw += __shfl_xor_sync(0xffffffffu, aw, 16);
        if (half == 0) out4[nd * 16 + hl] = make_float4(ax, ay, az, aw);
    }
}

// ------------- launch -------------
extern "C" void kernel_launch(void* const* d_in, const int* in_sizes, int n_in,
                              void* d_out, int out_size) {
    const float* x   = (const float*)d_in[0];
    const float* pos = (const float*)d_in[1];
    const int*   ei  = (const int*)d_in[2];   // int32 [2, E]
    const float* W1  = (const float*)d_in[3];
    const float* b1  = (const float*)d_in[4];
    const float* g1  = (const float*)d_in[5];
    const float* be1 = (const float*)d_in[6];
    const float* Wg  = (const float*)d_in[7];
    const float* bg  = (const float*)d_in[8];
    const float* gg  = (const float*)d_in[9];
    const float* bgb = (const float*)d_in[10];
    float* out = (float*)d_out;

    int n = in_sizes[0] / INCH;   // 100000
    int e = in_sizes[2] / 2;      // 1600000
    int nb = (n + SCAN_BLK - 1) / SCAN_BLK;

    k_init   <<<256, 256>>>(n);
    k_node   <<<512, 256>>>(x, pos, W1, n);
    k_count  <<<512, 256>>>(ei, e, n);
    k_scanA  <<<nb, SCAN_BLK>>>(n);
    k_scanB  <<<1, 128>>>(nb, n);
    k_scanC  <<<nb, SCAN_BLK>>>(n);
    k_scatter<<<512, 256>>>(ei, pos, e, n);
    k_zstats <<<256, 256>>>(b1, W1, n);
    k_bn1    <<<1, 64>>>(g1, be1, b1, (float)e);
    k_gate   <<<1024, 256>>>(b1, Wg, bg, n);
    k_bng    <<<1, 1>>>(gg, bgb, (float)e);
    k_agg    <<<1024, 256>>>(b1, out, n);
}